// round 12
// baseline (speedup 1.0000x reference)
#include <cuda_runtime.h>
#include <cstdint>

// ============================================================================
// ForexLSTM: 2-layer LSTM (B=512, T=1024, H=65) + final linear.
//
// R11: FUSED recurrence. One kernel runs BOTH LSTM layers with a 1-step skew:
//   iteration t computes layer0 step t and layer1 step t-1. Three matvec
//   thread-sets (260 each): set0 h0·Whh0 (+pre from smem), set1 h1·Wih1(+b1),
//   set2 h2·Whh1. set2 also prefetches pre[t+1] DRAM->smem (double-buffered).
//   set0 doubles as eltwise (both layers' cell updates, c in registers).
//   128 CTAs x 4 rows x 800 threads, 1 CTA/SM. No g_h1, no pre for layer 1.
// pre_kernel (layer 0 only) and final_linear unchanged.
// ============================================================================

using u32 = unsigned int;
using ull = unsigned long long;

constexpr int B = 512, T = 1024, H = 65, G4 = 260;
constexpr int PTHR = 288, PGRID = 296;
constexpr int TILE = 8;
constexpr int NTILES = (B * T) / TILE;
constexpr int FTHR = 800, FGRID = 128;        // fused: 4 rows per CTA

__device__ float g_pre[(size_t)B * T * G4];   // layer-0 pre-activations
__device__ float g_hN [B * H];                // layer-1 last-step h

// ---------------- helpers ----------------
__device__ __forceinline__ ull pack2(float x, float y) {
    ull r; asm("mov.b64 %0, {%1, %2};" : "=l"(r) : "f"(x), "f"(y)); return r;
}
__device__ __forceinline__ float2 unpack2(ull v) {
    float2 r; asm("mov.b64 {%0, %1}, %2;" : "=f"(r.x), "=f"(r.y) : "l"(v)); return r;
}
__device__ __forceinline__ void fma2(ull& d, ull a, ull b) {
    asm("fma.rn.f32x2 %0, %1, %2, %0;" : "+l"(d) : "l"(a), "l"(b));
}
__device__ __forceinline__ void lds128(ull& a, ull& b, u32 addr) {
    asm volatile("ld.shared.v2.u64 {%0, %1}, [%2];" : "=l"(a), "=l"(b) : "r"(addr));
}
__device__ __forceinline__ ull lds64(u32 addr) {
    ull a; asm volatile("ld.shared.u64 %0, [%1];" : "=l"(a) : "r"(addr)); return a;
}
__device__ __forceinline__ float lds32(u32 addr) {
    float v; asm volatile("ld.shared.f32 %0, [%1];" : "=f"(v) : "r"(addr)); return v;
}
__device__ __forceinline__ void sts32(u32 addr, float v) {
    asm volatile("st.shared.f32 [%0], %1;" :: "r"(addr), "f"(v) : "memory");
}
__device__ __forceinline__ float fast_sigmoid(float v) {
    return __fdividef(1.0f, 1.0f + __expf(-v));
}
__device__ __forceinline__ float fast_tanh(float v) {
    return 1.0f - 2.0f * __fdividef(1.0f, __expf(2.0f * v) + 1.0f);
}

// ============================================================================
// pre[row, g] = (b_ih0[g]+b_hh0[g]) + sum_i x[row,i] * w_ih0[g,i]   (layer 0)
// ============================================================================
__global__ void __launch_bounds__(PTHR, 2)
pre_kernel(const float* __restrict__ xin,
           const float* __restrict__ w_ih,
           const float* __restrict__ b_ih,
           const float* __restrict__ b_hh)
{
    __shared__ __align__(16) float xs[2][TILE * 68];
    const int tid = threadIdx.x;
    const bool act = tid < G4;

    ull wih[33]; float bg = 0.f;
    if (act) {
        const float* wi = w_ih + tid * H;
#pragma unroll
        for (int j = 0; j < 32; j++)
            wih[j] = pack2(__ldg(wi + 2 * j), __ldg(wi + 2 * j + 1));
        wih[32] = pack2(__ldg(wi + 64), 0.f);
        bg = __ldg(b_ih + tid) + __ldg(b_hh + tid);
    }
    for (int k = tid; k < 2 * TILE * 68; k += PTHR) (&xs[0][0])[k] = 0.f;
    __syncthreads();

    const int f0 = tid, f1 = tid + 260;
    const int s0 = (f0 / 65) * 68 + (f0 % 65);
    const int s1 = (f1 / 65) * 68 + (f1 % 65);

    int gi = blockIdx.x;
    if (act) {
        const float* src = xin + (size_t)gi * (TILE * H);
        xs[0][s0] = __ldg(src + f0);
        xs[0][s1] = __ldg(src + f1);
    }
    __syncthreads();

    const u32 xb = (u32)__cvta_generic_to_shared(&xs[0][0]);
    int cur = 0;
    for (; gi < NTILES; gi += PGRID) {
        const int gn = gi + PGRID;
        float xn0 = 0.f, xn1 = 0.f;
        if (act && gn < NTILES) {
            const float* src = xin + (size_t)gn * (TILE * H);
            xn0 = __ldg(src + f0);
            xn1 = __ldg(src + f1);
        }

        if (act) {
            const u32 bT = xb + cur * (TILE * 68 * 4);
#pragma unroll
            for (int sb = 0; sb < 2; sb++) {
                ull a0 = pack2(bg, 0.f), a1 = a0, a2 = a0, a3 = a0;
                const u32 bA = bT + sb * (4 * 272);
#pragma unroll
                for (int q = 0; q < 16; q++) {
                    ull u0, u1;
                    lds128(u0, u1, bA + 0 * 272 + q * 16);
                    fma2(a0, wih[2 * q], u0); fma2(a0, wih[2 * q + 1], u1);
                    lds128(u0, u1, bA + 1 * 272 + q * 16);
                    fma2(a1, wih[2 * q], u0); fma2(a1, wih[2 * q + 1], u1);
                    lds128(u0, u1, bA + 2 * 272 + q * 16);
                    fma2(a2, wih[2 * q], u0); fma2(a2, wih[2 * q + 1], u1);
                    lds128(u0, u1, bA + 3 * 272 + q * 16);
                    fma2(a3, wih[2 * q], u0); fma2(a3, wih[2 * q + 1], u1);
                }
                fma2(a0, wih[32], lds64(bA + 0 * 272 + 256));
                fma2(a1, wih[32], lds64(bA + 1 * 272 + 256));
                fma2(a2, wih[32], lds64(bA + 2 * 272 + 256));
                fma2(a3, wih[32], lds64(bA + 3 * 272 + 256));

                float* op = g_pre + ((size_t)gi * TILE + sb * 4) * G4 + tid;
                float2 s;
                s = unpack2(a0); op[0]      = s.x + s.y;
                s = unpack2(a1); op[G4]     = s.x + s.y;
                s = unpack2(a2); op[2 * G4] = s.x + s.y;
                s = unpack2(a3); op[3 * G4] = s.x + s.y;
            }
        }
        if (act && gn < NTILES) {
            xs[cur ^ 1][s0] = xn0;
            xs[cur ^ 1][s1] = xn1;
        }
        __syncthreads();
        cur ^= 1;
    }
}

// ============================================================================
// Fused 2-layer recurrence with 1-step skew.
// ============================================================================
__global__ void __launch_bounds__(FTHR, 1)
fused_kernel(const float* __restrict__ w_hh0,
             const float* __restrict__ w_ih1,
             const float* __restrict__ w_hh1,
             const float* __restrict__ b_ih1,
             const float* __restrict__ b_hh1)
{
    __shared__ __align__(16) float hA_sm[4 * 68];   // layer0 hidden
    __shared__ __align__(16) float hB_sm[4 * 68];   // layer1 hidden
    __shared__ float gA_sm[4 * G4];                 // layer0 raw gates
    __shared__ float g1_sm[4 * G4];                 // layer1 partial (h1·Wih1+b)
    __shared__ float g2_sm[4 * G4];                 // layer1 partial (h2·Whh1)
    __shared__ float pre_sm[2][4 * G4];             // staged pre[t] (dbl-buf)

    const int tid = threadIdx.x;
    const int b0  = blockIdx.x * 4;
    const bool act = tid < 780;
    const int setid = act ? (tid / G4) : 0;
    const int g     = act ? (tid % G4) : 0;

    // ---- per-thread weights (one gate row of one matrix) ----
    const float* wb = (setid == 0) ? w_hh0 : ((setid == 1) ? w_ih1 : w_hh1);
    ull wv[32]; float w64 = 0.f, bg1 = 0.f;
    if (act) {
        const float* wr = wb + g * H;
#pragma unroll
        for (int q = 0; q < 32; q++)
            wv[q] = pack2(__ldg(wr + 2 * q), __ldg(wr + 2 * q + 1));
        w64 = __ldg(wr + 64);
        if (setid == 1) bg1 = __ldg(b_ih1 + g) + __ldg(b_hh1 + g);
    }

    // ---- init ----
    for (int k = tid; k < 4 * 68; k += FTHR) { hA_sm[k] = 0.f; hB_sm[k] = 0.f; }

    const float* pbase = g_pre + (size_t)b0 * T * G4 + g;  // row b0, t=0
    if (act && setid == 2) {
#pragma unroll
        for (int r = 0; r < 4; r++)
            pre_sm[0][r * G4 + g] = __ldg(pbase + ((size_t)r * T) * G4);
    }
    __syncthreads();

    const u32 hAb = (u32)__cvta_generic_to_shared(hA_sm);
    const u32 hBb = (u32)__cvta_generic_to_shared(hB_sm);
    const u32 gAb = (u32)__cvta_generic_to_shared(gA_sm);
    const u32 g1b = (u32)__cvta_generic_to_shared(g1_sm);
    const u32 g2b = (u32)__cvta_generic_to_shared(g2_sm);
    const u32 prb = (u32)__cvta_generic_to_shared(&pre_sm[0][0]);

    const u32 hbase  = (setid == 2) ? hBb : hAb;
    const u32 outb   = ((setid == 0) ? gAb : ((setid == 1) ? g1b : g2b)) + g * 4;

    // eltwise identity (set0 threads only)
    const int r_e = g / 65, j_e = g % 65;
    float cA = 0.f, cB = 0.f;

    for (int t = 0; t <= T; t++) {
        const int cur = t & 1;

        if (act) {
            const bool domv = (setid == 0) ? (t < T) : (t >= 1);
            if (domv) {
                // per-row additive term
                float add0, add1, add2, add3;
                if (setid == 0) {
                    const u32 pb = prb + cur * (4 * G4 * 4) + g * 4;
                    add0 = lds32(pb);
                    add1 = lds32(pb + G4 * 4);
                    add2 = lds32(pb + 2 * G4 * 4);
                    add3 = lds32(pb + 3 * G4 * 4);
                } else if (setid == 1) {
                    add0 = add1 = add2 = add3 = bg1;
                } else {
                    add0 = add1 = add2 = add3 = 0.f;
                }
#pragma unroll
                for (int r = 0; r < 4; r++) {
                    ull a0 = 0ull, a1 = 0ull;
                    const u32 hr = hbase + r * 272;
#pragma unroll
                    for (int q = 0; q < 8; q++) {
                        ull u0, u1, u2, u3;
                        lds128(u0, u1, hr + q * 32);
                        lds128(u2, u3, hr + q * 32 + 16);
                        fma2(a0, wv[4 * q],     u0);
                        fma2(a1, wv[4 * q + 1], u1);
                        fma2(a0, wv[4 * q + 2], u2);
                        fma2(a1, wv[4 * q + 3], u3);
                    }
                    float h64 = lds32(hr + 256);
                    float2 s0 = unpack2(a0), s1 = unpack2(a1);
                    float add = (r == 0) ? add0 : (r == 1) ? add1 : (r == 2) ? add2 : add3;
                    float v = ((s0.x + s0.y) + (s1.x + s1.y)) + fmaf(w64, h64, add);
                    sts32(outb + r * (G4 * 4), v);
                }
            }
            // set2 prefetches pre[t+1] into the other buffer
            if (setid == 2 && t + 1 < T) {
#pragma unroll
                for (int r = 0; r < 4; r++) {
                    float pn = __ldg(pbase + ((size_t)r * T + (t + 1)) * G4);
                    sts32(prb + (cur ^ 1) * (4 * G4 * 4) + (r * G4 + g) * 4, pn);
                }
            }
        }
        __syncthreads();

        // ---- phase 2: eltwise on set0 ----
        if (act && setid == 0) {
            const u32 base = r_e * (G4 * 4) + j_e * 4;
            if (t < T) {
                float vi = lds32(gAb + base);
                float vf = lds32(gAb + base + 65 * 4);
                float vg = lds32(gAb + base + 130 * 4);
                float vo = lds32(gAb + base + 195 * 4);
                float iv = fast_sigmoid(vi);
                float fv = fast_sigmoid(vf);
                float gv = fast_tanh(vg);
                float ov = fast_sigmoid(vo);
                cA = fv * cA + iv * gv;
                hA_sm[r_e * 68 + j_e] = ov * fast_tanh(cA);
            }
            if (t >= 1) {
                float vi = lds32(g1b + base)           + lds32(g2b + base);
                float vf = lds32(g1b + base + 65 * 4)  + lds32(g2b + base + 65 * 4);
                float vg = lds32(g1b + base + 130 * 4) + lds32(g2b + base + 130 * 4);
                float vo = lds32(g1b + base + 195 * 4) + lds32(g2b + base + 195 * 4);
                float iv = fast_sigmoid(vi);
                float fv = fast_sigmoid(vf);
                float gv = fast_tanh(vg);
                float ov = fast_sigmoid(vo);
                cB = fv * cB + iv * gv;
                float hBv = ov * fast_tanh(cB);
                hB_sm[r_e * 68 + j_e] = hBv;
                if (t == T) g_hN[(size_t)(b0 + r_e) * H + j_e] = hBv;
            }
        }
        __syncthreads();
    }
}

// ============================================================================
// out[b] = g_hN[b,:] . w_lin + b_lin
// ============================================================================
__global__ void final_linear_kernel(const float* __restrict__ w_lin,
                                    const float* __restrict__ b_lin,
                                    float* __restrict__ out)
{
    __shared__ float w[72];
    const int tid = threadIdx.x;
    if (tid < H) w[tid] = __ldg(w_lin + tid);
    __syncthreads();
    const int b = blockIdx.x * blockDim.x + tid;
    if (b < B) {
        const float* h = g_hN + (size_t)b * H;
        float s = __ldg(b_lin);
#pragma unroll
        for (int i = 0; i < H; i++) s += h[i] * w[i];
        out[b] = s;
    }
}

// ============================================================================
extern "C" void kernel_launch(void* const* d_in, const int* in_sizes, int n_in,
                              void* d_out, int out_size)
{
    const float* x     = (const float*)d_in[0];
    const float* w_ih0 = (const float*)d_in[1];
    const float* w_hh0 = (const float*)d_in[2];
    const float* b_ih0 = (const float*)d_in[3];
    const float* b_hh0 = (const float*)d_in[4];
    const float* w_ih1 = (const float*)d_in[5];
    const float* w_hh1 = (const float*)d_in[6];
    const float* b_ih1 = (const float*)d_in[7];
    const float* b_hh1 = (const float*)d_in[8];
    const float* w_lin = (const float*)d_in[9];
    const float* b_lin = (const float*)d_in[10];

    pre_kernel<<<PGRID, PTHR>>>(x, w_ih0, b_ih0, b_hh0);
    fused_kernel<<<FGRID, FTHR>>>(w_hh0, w_ih1, w_hh1, b_ih1, b_hh1);
    final_linear_kernel<<<2, 256>>>(w_lin, b_lin, (float*)d_out);
}

// round 16
// speedup vs baseline: 1.5113x; 1.5113x over previous
#include <cuda_runtime.h>
#include <cstdint>

// ============================================================================
// ForexLSTM: 2-layer LSTM (B=512, T=1024, H=65) + final linear.
//
// R12: 2-gates-per-thread everywhere. Gates g and g+130 share one h/x stream:
//  4 FMA2 per LDS.128 instead of 2 -> the LDS-bound pipe (measured ~55-75% L1)
//  is cut in half. 130 active threads per CTA, ~185 regs (66 ull weights),
//  __launch_bounds__(160,2) -> 2 CTAs/SM, no spills.
//  - pre_kernel: 8-row tiles, 2 sub-blocks x 4 rows x 2 gates (8 accums).
//  - recur_kernel: 256 CTAs x 2 rows; same 2-barrier skeleton as R8; eltwise
//    on the same 130 threads (unit j = tid%65, row = tid/65).
// ============================================================================

using u32 = unsigned int;
using ull = unsigned long long;

constexpr int B = 512, T = 1024, H = 65, G4 = 260;
constexpr int PTHR = 160, PGRID = 296;
constexpr int TILE = 8;
constexpr int NTILES = (B * T) / TILE;        // 65536
constexpr int RTHR = 160, RGRID = 256;        // 2 rows per CTA

__device__ float g_pre[(size_t)B * T * G4];   // layer-0/1 pre-activations
__device__ float g_h1 [(size_t)B * T * H];    // layer-0 output sequence
__device__ float g_hN [B * H];                // layer-1 last-step h

// ---------------- helpers ----------------
__device__ __forceinline__ ull pack2(float x, float y) {
    ull r; asm("mov.b64 %0, {%1, %2};" : "=l"(r) : "f"(x), "f"(y)); return r;
}
__device__ __forceinline__ float2 unpack2(ull v) {
    float2 r; asm("mov.b64 {%0, %1}, %2;" : "=f"(r.x), "=f"(r.y) : "l"(v)); return r;
}
__device__ __forceinline__ void fma2(ull& d, ull a, ull b) {
    asm("fma.rn.f32x2 %0, %1, %2, %0;" : "+l"(d) : "l"(a), "l"(b));
}
__device__ __forceinline__ void lds128(ull& a, ull& b, u32 addr) {
    asm volatile("ld.shared.v2.u64 {%0, %1}, [%2];" : "=l"(a), "=l"(b) : "r"(addr));
}
__device__ __forceinline__ ull lds64(u32 addr) {
    ull a; asm volatile("ld.shared.u64 %0, [%1];" : "=l"(a) : "r"(addr)); return a;
}
__device__ __forceinline__ float lds32(u32 addr) {
    float v; asm volatile("ld.shared.f32 %0, [%1];" : "=f"(v) : "r"(addr)); return v;
}
__device__ __forceinline__ void sts64v(u32 addr, float x, float y) {
    asm volatile("st.shared.v2.f32 [%0], {%1, %2};" :: "r"(addr), "f"(x), "f"(y) : "memory");
}
__device__ __forceinline__ float fast_sigmoid(float v) {
    return __fdividef(1.0f, 1.0f + __expf(-v));
}
__device__ __forceinline__ float fast_tanh(float v) {
    return 1.0f - 2.0f * __fdividef(1.0f, __expf(2.0f * v) + 1.0f);
}

// ============================================================================
// pre[row, g] = (b_ih[g]+b_hh[g]) + sum_i xin[row,i] * w_ih[g,i]
// 8-row double-buffered tiles; thread owns gates {tid, tid+130}.
// ============================================================================
__global__ void __launch_bounds__(PTHR, 2)
pre_kernel(const float* __restrict__ x_ext,
           const float* __restrict__ w_ih,
           const float* __restrict__ b_ih,
           const float* __restrict__ b_hh,
           int layer)
{
    const float* xin = (layer == 0) ? x_ext : g_h1;

    __shared__ __align__(16) float xs[2][TILE * 68];
    const int tid = threadIdx.x;
    const bool act = tid < 130;
    const int gA = tid, gB = tid + 130;

    ull wA[33], wB[33]; float bgA = 0.f, bgB = 0.f;
    if (act) {
        const float* wa = w_ih + gA * H;
        const float* wb = w_ih + gB * H;
#pragma unroll
        for (int j = 0; j < 32; j++) {
            wA[j] = pack2(__ldg(wa + 2 * j), __ldg(wa + 2 * j + 1));
            wB[j] = pack2(__ldg(wb + 2 * j), __ldg(wb + 2 * j + 1));
        }
        wA[32] = pack2(__ldg(wa + 64), 0.f);
        wB[32] = pack2(__ldg(wb + 64), 0.f);
        bgA = __ldg(b_ih + gA) + __ldg(b_hh + gA);
        bgB = __ldg(b_ih + gB) + __ldg(b_hh + gB);
    }
    for (int k = tid; k < 2 * TILE * 68; k += PTHR) (&xs[0][0])[k] = 0.f;
    __syncthreads();

    // staging: tile = 8 rows = 520 contiguous floats; active thread loads 4
    int sidx[4];
#pragma unroll
    for (int k = 0; k < 4; k++) {
        int f = tid + k * 130;
        sidx[k] = (f / 65) * 68 + (f % 65);
    }

    int gi = blockIdx.x;
    if (act) {
        const float* src = xin + (size_t)gi * (TILE * H);
#pragma unroll
        for (int k = 0; k < 4; k++) xs[0][sidx[k]] = __ldg(src + tid + k * 130);
    }
    __syncthreads();

    const u32 xb = (u32)__cvta_generic_to_shared(&xs[0][0]);
    int cur = 0;
    for (; gi < NTILES; gi += PGRID) {
        const int gn = gi + PGRID;
        float xn[4] = {0.f, 0.f, 0.f, 0.f};
        if (act && gn < NTILES) {
            const float* src = xin + (size_t)gn * (TILE * H);
#pragma unroll
            for (int k = 0; k < 4; k++) xn[k] = __ldg(src + tid + k * 130);
        }

        if (act) {
            const u32 bT = xb + cur * (TILE * 68 * 4);
#pragma unroll
            for (int sb = 0; sb < 2; sb++) {
                ull aA[4], aB[4];
#pragma unroll
                for (int r = 0; r < 4; r++) {
                    aA[r] = pack2(bgA, 0.f);
                    aB[r] = pack2(bgB, 0.f);
                }
                const u32 bA = bT + sb * (4 * 272);
#pragma unroll
                for (int q = 0; q < 16; q++) {
#pragma unroll
                    for (int r = 0; r < 4; r++) {
                        ull u0, u1;
                        lds128(u0, u1, bA + r * 272 + q * 16);
                        fma2(aA[r], wA[2 * q], u0); fma2(aA[r], wA[2 * q + 1], u1);
                        fma2(aB[r], wB[2 * q], u0); fma2(aB[r], wB[2 * q + 1], u1);
                    }
                }
#pragma unroll
                for (int r = 0; r < 4; r++) {
                    ull t64 = lds64(bA + r * 272 + 256);
                    fma2(aA[r], wA[32], t64);
                    fma2(aB[r], wB[32], t64);
                }
                float* op = g_pre + ((size_t)gi * TILE + sb * 4) * G4;
#pragma unroll
                for (int r = 0; r < 4; r++) {
                    float2 sa = unpack2(aA[r]);
                    float2 sb2 = unpack2(aB[r]);
                    op[(size_t)r * G4 + gA] = sa.x + sa.y;
                    op[(size_t)r * G4 + gB] = sb2.x + sb2.y;
                }
            }
        }
        if (act && gn < NTILES) {
#pragma unroll
            for (int k = 0; k < 4; k++) xs[cur ^ 1][sidx[k]] = xn[k];
        }
        __syncthreads();
        cur ^= 1;
    }
}

// ============================================================================
// Recurrent kernel: gates = pre[t] + h·W_hh^T (raw), eltwise applies
// activations + cell update. 256 CTAs x 2 rows, 160 threads (130 active),
// 2 CTAs/SM. Thread owns gates {tid, tid+130}; eltwise: unit tid%65, row tid/65.
// ============================================================================
__global__ void __launch_bounds__(RTHR, 2)
recur_kernel(const float* __restrict__ w_hh, int write_all)
{
    __shared__ __align__(16) float h_sm[2 * 68];
    __shared__ __align__(8)  float gates_sm[G4 * 2];   // [g][row]

    const int tid = threadIdx.x;
    const int b0  = blockIdx.x * 2;
    const bool act = tid < 130;
    const int gA = tid, gB = tid + 130;

    ull wA[33], wB[33];
    if (act) {
        const float* wa = w_hh + gA * H;
        const float* wb = w_hh + gB * H;
#pragma unroll
        for (int k = 0; k < 32; k++) {
            wA[k] = pack2(__ldg(wa + 2 * k), __ldg(wa + 2 * k + 1));
            wB[k] = pack2(__ldg(wb + 2 * k), __ldg(wb + 2 * k + 1));
        }
        wA[32] = pack2(__ldg(wa + 64), 0.f);
        wB[32] = pack2(__ldg(wb + 64), 0.f);
    }

    const int r_e = act ? (tid / 65) : 0;   // eltwise row
    const int j_e = act ? (tid % 65) : 0;   // eltwise unit

    const float* pA0 = g_pre + ((size_t)(b0 + 0) * T) * G4 + gA;
    const float* pA1 = g_pre + ((size_t)(b0 + 1) * T) * G4 + gA;
    const float* pB0 = g_pre + ((size_t)(b0 + 0) * T) * G4 + gB;
    const float* pB1 = g_pre + ((size_t)(b0 + 1) * T) * G4 + gB;
    float* op = write_all ? g_h1 + ((size_t)(b0 + r_e) * T) * H + j_e
                          : g_hN + (size_t)(b0 + r_e) * H + j_e;

    for (int k = tid; k < 2 * 68; k += RTHR) h_sm[k] = 0.f;
    __syncthreads();

    const u32 hb = (u32)__cvta_generic_to_shared(h_sm);
    const u32 gb = (u32)__cvta_generic_to_shared(gates_sm);
    float c = 0.f;
    float pvA0 = 0.f, pvA1 = 0.f, pvB0 = 0.f, pvB1 = 0.f;
    if (act) {
        pvA0 = __ldg(pA0); pvA1 = __ldg(pA1);
        pvB0 = __ldg(pB0); pvB1 = __ldg(pB1);
    }

    for (int t = 0; t < T; t++) {
        float pnA0 = 0.f, pnA1 = 0.f, pnB0 = 0.f, pnB1 = 0.f;
        if (act && t + 1 < T) {
            const size_t o = (size_t)(t + 1) * G4;
            pnA0 = __ldg(pA0 + o); pnA1 = __ldg(pA1 + o);
            pnB0 = __ldg(pB0 + o); pnB1 = __ldg(pB1 + o);
        }

        if (act) {
            // row 0: both gates share the h loads (4 FMA2 per LDS.128)
            ull aA0 = 0ull, aA1 = 0ull, aB0 = 0ull, aB1 = 0ull;
            ull cA0 = 0ull, cA1 = 0ull, cB0 = 0ull, cB1 = 0ull;
            const u32 h0 = hb;
            const u32 h1 = hb + 272;
#pragma unroll
            for (int q = 0; q < 8; q++) {
                ull u0, u1, u2, u3;
                lds128(u0, u1, h0 + q * 32);
                lds128(u2, u3, h0 + q * 32 + 16);
                fma2(aA0, wA[4 * q],     u0); fma2(aA1, wA[4 * q + 1], u1);
                fma2(aA0, wA[4 * q + 2], u2); fma2(aA1, wA[4 * q + 3], u3);
                fma2(aB0, wB[4 * q],     u0); fma2(aB1, wB[4 * q + 1], u1);
                fma2(aB0, wB[4 * q + 2], u2); fma2(aB1, wB[4 * q + 3], u3);
            }
#pragma unroll
            for (int q = 0; q < 8; q++) {
                ull u0, u1, u2, u3;
                lds128(u0, u1, h1 + q * 32);
                lds128(u2, u3, h1 + q * 32 + 16);
                fma2(cA0, wA[4 * q],     u0); fma2(cA1, wA[4 * q + 1], u1);
                fma2(cA0, wA[4 * q + 2], u2); fma2(cA1, wA[4 * q + 3], u3);
                fma2(cB0, wB[4 * q],     u0); fma2(cB1, wB[4 * q + 1], u1);
                fma2(cB0, wB[4 * q + 2], u2); fma2(cB1, wB[4 * q + 3], u3);
            }
            {
                ull t0 = lds64(h0 + 256);
                ull t1 = lds64(h1 + 256);
                fma2(aA0, wA[32], t0); fma2(aB0, wB[32], t0);
                fma2(cA0, wA[32], t1); fma2(cB0, wB[32], t1);
            }

            float2 s;
            s = unpack2(aA0); float vA0 = s.x + s.y;
            s = unpack2(aA1); vA0 += s.x + s.y; vA0 += pvA0;
            s = unpack2(cA0); float vA1 = s.x + s.y;
            s = unpack2(cA1); vA1 += s.x + s.y; vA1 += pvA1;
            s = unpack2(aB0); float vB0 = s.x + s.y;
            s = unpack2(aB1); vB0 += s.x + s.y; vB0 += pvB0;
            s = unpack2(cB0); float vB1 = s.x + s.y;
            s = unpack2(cB1); vB1 += s.x + s.y; vB1 += pvB1;

            sts64v(gb + gA * 8, vA0, vA1);
            sts64v(gb + gB * 8, vB0, vB1);
        }
        __syncthreads();

        if (act) {
            const u32 ga = gb + r_e * 4;
            float vi = lds32(ga + (j_e)       * 8);
            float vf = lds32(ga + (65 + j_e)  * 8);
            float vg = lds32(ga + (130 + j_e) * 8);
            float vo = lds32(ga + (195 + j_e) * 8);
            float iv = fast_sigmoid(vi);
            float fv = fast_sigmoid(vf);
            float gv = fast_tanh(vg);
            float ov = fast_sigmoid(vo);
            c = fv * c + iv * gv;
            float hv = ov * fast_tanh(c);
            h_sm[r_e * 68 + j_e] = hv;
            if (write_all)        op[(size_t)t * H] = hv;
            else if (t == T - 1)  op[0] = hv;
        }
        pvA0 = pnA0; pvA1 = pnA1; pvB0 = pnB0; pvB1 = pnB1;
        __syncthreads();
    }
}

// ============================================================================
// out[b] = g_hN[b,:] . w_lin + b_lin
// ============================================================================
__global__ void final_linear_kernel(const float* __restrict__ w_lin,
                                    const float* __restrict__ b_lin,
                                    float* __restrict__ out)
{
    __shared__ float w[72];
    const int tid = threadIdx.x;
    if (tid < H) w[tid] = __ldg(w_lin + tid);
    __syncthreads();
    const int b = blockIdx.x * blockDim.x + tid;
    if (b < B) {
        const float* h = g_hN + (size_t)b * H;
        float s = __ldg(b_lin);
#pragma unroll
        for (int i = 0; i < H; i++) s += h[i] * w[i];
        out[b] = s;
    }
}

// ============================================================================
extern "C" void kernel_launch(void* const* d_in, const int* in_sizes, int n_in,
                              void* d_out, int out_size)
{
    const float* x     = (const float*)d_in[0];
    const float* w_ih0 = (const float*)d_in[1];
    const float* w_hh0 = (const float*)d_in[2];
    const float* b_ih0 = (const float*)d_in[3];
    const float* b_hh0 = (const float*)d_in[4];
    const float* w_ih1 = (const float*)d_in[5];
    const float* w_hh1 = (const float*)d_in[6];
    const float* b_ih1 = (const float*)d_in[7];
    const float* b_hh1 = (const float*)d_in[8];
    const float* w_lin = (const float*)d_in[9];
    const float* b_lin = (const float*)d_in[10];

    pre_kernel<<<PGRID, PTHR>>>(x, w_ih0, b_ih0, b_hh0, 0);
    recur_kernel<<<RGRID, RTHR>>>(w_hh0, 1);
    pre_kernel<<<PGRID, PTHR>>>(x, w_ih1, b_ih1, b_hh1, 1);
    recur_kernel<<<RGRID, RTHR>>>(w_hh1, 0);
    final_linear_kernel<<<2, 256>>>(w_lin, b_lin, (float*)d_out);
}